// round 1
// baseline (speedup 1.0000x reference)
#include <cuda_runtime.h>
#include <math.h>

// ---------------- problem dims ----------------
#define Bq    4
#define NM    4
#define TT    1024
#define DD    256
#define DKc   16
#define DVc   64
#define DKPc  32
#define Hc    8
#define Ec    4
#define HEc   32
#define Rc    4
#define DAc   25
#define DPGc  316
#define NDc   1024
#define DATTNc 512
#define BT    (Bq*TT)   // 4096

// ---------------- scratch (device globals; no allocation allowed) ----------------
__device__ float g_xhat [BT*NDc];
__device__ float g_route[BT*DD];
__device__ int   g_qsel [Hc*BT];
__device__ int   g_kvsel[Hc*BT];
__device__ float g_q [Hc*BT*DKPc];
__device__ float g_k [Hc*BT*DKPc];
__device__ float g_a [Hc*BT*DKPc];
__device__ float g_v [Hc*BT*DVc];
__device__ float g_be[Hc*BT];
__device__ float g_accpre [BT*DATTNc];
__device__ float g_accpost[BT*DD];
__device__ float g_accres [BT*16];
__device__ float g_acchp  [BT*4];
__device__ float g_o  [Hc*BT*DVc];
__device__ float g_res[BT*DD];

// ---------------- helpers ----------------
__device__ __forceinline__ float sigmoidf_(float x){ return 1.f/(1.f+expf(-x)); }
__device__ __forceinline__ float siluf_(float x){ return x/(1.f+expf(-x)); }
__device__ __forceinline__ float softplusf_(float x){ return fmaxf(x,0.f)+log1pf(expf(-fabsf(x))); }

__device__ __forceinline__ float warpSum(float v){
    #pragma unroll
    for(int o=16;o;o>>=1) v += __shfl_xor_sync(0xffffffffu, v, o);
    return v;
}
// 256-thread block reduce (all threads must call)
__device__ __forceinline__ float blockSum256(float v, float* sred){
    int lane=threadIdx.x&31, wid=threadIdx.x>>5;
    v = warpSum(v);
    if(lane==0) sred[wid]=v;
    __syncthreads();
    if(wid==0){
        float x = (lane<8)? sred[lane] : 0.f;
        x = warpSum(x);
        if(lane==0) sred[0]=x;
    }
    __syncthreads();
    float r = sred[0];
    __syncthreads();
    return r;
}

// ---------------- kernel 1: x_hat + route_in ----------------
__global__ void k_prep(const float* __restrict__ stream){
    int bt=blockIdx.x, tid=threadIdx.x;
    int b=bt>>10, t=bt&1023;
    __shared__ float sred[8];
    float v[NM]; float ss=0.f;
    #pragma unroll
    for(int n=0;n<NM;n++){
        v[n]=stream[(((b*NM+n)*TT)+t)*DD+tid];
        ss += v[n]*v[n];
    }
    float tot = blockSum256(ss, sred);
    float scale = rsqrtf(tot*(1.f/1024.f) + 1e-6f);
    #pragma unroll
    for(int n=0;n<NM;n++) g_xhat[(size_t)bt*NDc + n*DD + tid] = v[n]*scale;
    g_route[bt*DD+tid] = (v[0]+v[1]+v[2]+v[3])*0.25f;
}

// ---------------- kernel 2: routing (argmax of clipped logits) ----------------
__global__ void k_route(const float* __restrict__ q_router, const float* __restrict__ kv_router){
    int bt=blockIdx.x; int tid=threadIdx.x; int lane=tid&31, h=tid>>5;
    __shared__ float r[DD];
    r[tid]=g_route[bt*DD+tid];
    __syncthreads();
    float aq[4]={0,0,0,0}, ak[4]={0,0,0,0};
    for(int d=lane; d<DD; d+=32){
        float x=r[d];
        const float* wq=q_router + (h*DD+d)*Ec;
        const float* wk=kv_router+ (h*DD+d)*Ec;
        #pragma unroll
        for(int e=0;e<4;e++){ aq[e]+=x*wq[e]; ak[e]+=x*wk[e]; }
    }
    #pragma unroll
    for(int e=0;e<4;e++){ aq[e]=warpSum(aq[e]); ak[e]=warpSum(ak[e]); }
    if(lane==0){
        int bqi=0; float bv=fminf(fmaxf(aq[0],-10.f),10.f);
        #pragma unroll
        for(int e=1;e<4;e++){ float c=fminf(fmaxf(aq[e],-10.f),10.f); if(c>bv){bv=c;bqi=e;} }
        int bki=0; float kvb=fminf(fmaxf(ak[0],-10.f),10.f);
        #pragma unroll
        for(int e=1;e<4;e++){ float c=fminf(fmaxf(ak[e],-10.f),10.f); if(c>kvb){kvb=c;bki=e;} }
        g_qsel [h*BT+bt]=bqi;
        g_kvsel[h*BT+bt]=bki;
    }
}

// ---------------- kernel 3: per-token main (H features + all projections) ----------------
__global__ void __launch_bounds__(256) k_main(
    const float* __restrict__ stream,
    const float* __restrict__ Wq, const float* __restrict__ Wk, const float* __restrict__ Wv,
    const float* __restrict__ pope_delta,
    const float* __restrict__ lora_A_q, const float* __restrict__ lora_B_q,
    const float* __restrict__ lora_A_k, const float* __restrict__ lora_B_k,
    const float* __restrict__ lora_A_v, const float* __restrict__ lora_B_v,
    const float* __restrict__ alpha_up, const float* __restrict__ alpha_down,
    const float* __restrict__ beta_up,  const float* __restrict__ beta_down,
    const float* __restrict__ mhc_norm_w,
    const float* __restrict__ phi_pre, const float* __restrict__ phi_post, const float* __restrict__ phi_res,
    const float* __restrict__ b_pre, const float* __restrict__ b_post, const float* __restrict__ b_res,
    const float* __restrict__ a_pre, const float* __restrict__ a_post, const float* __restrict__ a_res,
    const float* __restrict__ norm_w,
    const float* __restrict__ W_pre,
    const float* __restrict__ W_pg1, const float* __restrict__ W_pg2)
{
    int bt=blockIdx.x, tid=threadIdx.x;
    int b=bt>>10, t=bt&1023;
    int lane=tid&31, wid=tid>>5;

    __shared__ float xh[NDc];
    __shared__ float she[DD];
    __shared__ float smid[DPGc];
    __shared__ float sdots[28];
    __shared__ float sHq[4], sHkv[4];
    __shared__ float skraw[16], svraw[64], sam[25], sbm[25], slk[4], slv[4], skvec[16];
    __shared__ float sacc_pre[DATTNc];
    __shared__ float sacc_post[DD];
    __shared__ float sacc_res[16];
    __shared__ float sacc_hp[4];
    __shared__ float sred[8];
    __shared__ float sfreq[16], sshift[16];

    for(int i=tid;i<NDc;i+=256) xh[i]=g_xhat[(size_t)bt*NDc+i];
    for(int i=tid;i<DATTNc;i+=256) sacc_pre[i]=0.f;
    sacc_post[tid]=0.f;
    if(tid<16) sacc_res[tid]=0.f;
    if(tid<4)  sacc_hp[tid]=0.f;
    if(tid<16){
        sfreq[tid]  = (float)pow(10000.0, ((double)tid)/16.0);
        sshift[tid] = 6.283185307179586f * sigmoidf_(pope_delta[tid]);
    }
    __syncthreads();

    for(int h=0;h<Hc;h++){
        int eq  = g_qsel [h*BT+bt];
        int ekv = g_kvsel[h*BT+bt];
        int heq = h*Ec+eq, hekv = h*Ec+ekv;

        // ---- Phase A: 28 length-1024 dots against x_hat ----
        for(int j=wid;j<28;j+=8){
            const float* phi; int hh; int stride;
            if(j<4)      { hh=heq;  phi=phi_pre +(size_t)heq *NDc*4  + j;      stride=4; }
            else if(j<8) { hh=hekv; phi=phi_pre +(size_t)hekv*NDc*4  + (j-4);  stride=4; }
            else if(j<12){ hh=hekv; phi=phi_post+(size_t)hekv*NDc*4  + (j-8);  stride=4; }
            else         { hh=hekv; phi=phi_res +(size_t)hekv*NDc*16 + (j-12); stride=16;}
            const float* nw = mhc_norm_w + (size_t)hh*NDc;
            float s=0.f;
            for(int k=lane;k<NDc;k+=32) s += xh[k]*nw[k]*phi[(size_t)k*stride];
            s = warpSum(s);
            if(lane==0) sdots[j]=s;
        }
        __syncthreads();

        // ---- Phase B: sigmoids + sinkhorn (thread 0) ----
        if(tid==0){
            float apq=a_pre[heq], apk=a_pre[hekv], apo=a_post[hekv], ars=a_res[hekv];
            #pragma unroll
            for(int n=0;n<4;n++){
                sHq [n] = sigmoidf_(apq*sdots[n]   + b_pre[heq*4+n]);
                sHkv[n] = sigmoidf_(apk*sdots[4+n] + b_pre[hekv*4+n]);
                float hp = 2.f*sigmoidf_(apo*sdots[8+n] + b_post[hekv*4+n]);
                sacc_hp[n] += hp;
            }
            float M[16];
            #pragma unroll
            for(int m=0;m<16;m++) M[m]=expf(ars*sdots[12+m] + b_res[hekv*16+m]);
            #pragma unroll
            for(int it=0;it<6;it++){
                #pragma unroll
                for(int i=0;i<4;i++){ float s=M[i*4]+M[i*4+1]+M[i*4+2]+M[i*4+3];
                    M[i*4]/=s; M[i*4+1]/=s; M[i*4+2]/=s; M[i*4+3]/=s; }
                #pragma unroll
                for(int j=0;j<4;j++){ float s=M[j]+M[4+j]+M[8+j]+M[12+j];
                    M[j]/=s; M[4+j]/=s; M[8+j]/=s; M[12+j]/=s; }
            }
            #pragma unroll
            for(int m=0;m<16;m++) sacc_res[m]+=M[m];
        }
        __syncthreads();

        // ---- Phase C: he for kv expert (rms * norm_w) ----
        {
            float v=0.f;
            #pragma unroll
            for(int n=0;n<4;n++) v += sHkv[n]*stream[(((b*NM+n)*TT)+t)*DD+tid];
            float tot = blockSum256(v*v, sred);
            float sc = rsqrtf(tot*(1.f/256.f)+1e-6f);
            she[tid] = v*sc*norm_w[hekv*DD+tid];
        }
        __syncthreads();

        // ---- Phase D stage 1: all dot(256) projections from she ----
        for(int o=tid;o<DATTNc;o+=256){
            const float* w = W_pre + (size_t)hekv*DD*DATTNc + o;
            float s=0.f;
            #pragma unroll 8
            for(int d=0;d<DD;d++) s += she[d]*w[(size_t)d*DATTNc];
            sacc_pre[o] += siluf_(s)*0.125f;
        }
        if(tid<64){
            const float* w = Wv + (size_t)h*DD*DVc + tid;
            float s=0.f;
            #pragma unroll 8
            for(int d=0;d<DD;d++) s += she[d]*w[d*DVc];
            svraw[tid]=s;
        }
        if(tid<16){
            const float* w = Wk + (size_t)h*DD*DKc + tid;
            float s=0.f;
            #pragma unroll 8
            for(int d=0;d<DD;d++) s += she[d]*w[d*DKc];
            skraw[tid]=s;
        }
        if(tid>=64 && tid<89){
            int r=tid-64;
            const float* w = alpha_up + (size_t)hekv*DD*DAc + r;
            float s=0.f;
            #pragma unroll 8
            for(int d=0;d<DD;d++) s += she[d]*w[d*DAc];
            sam[r]=siluf_(s);
        }
        if(tid>=96 && tid<121){
            int r=tid-96;
            const float* w = beta_up + (size_t)hekv*DD*DAc + r;
            float s=0.f;
            #pragma unroll 8
            for(int d=0;d<DD;d++) s += she[d]*w[d*DAc];
            sbm[r]=siluf_(s);
        }
        if(tid>=128 && tid<132){
            int r=tid-128;
            const float* w = lora_A_k + (size_t)hekv*DD*Rc + r;
            float s=0.f;
            #pragma unroll 8
            for(int d=0;d<DD;d++) s += she[d]*w[d*Rc];
            slk[r]=siluf_(s);
        }
        if(tid>=132 && tid<136){
            int r=tid-132;
            const float* w = lora_A_v + (size_t)hekv*DD*Rc + r;
            float s=0.f;
            #pragma unroll 8
            for(int d=0;d<DD;d++) s += she[d]*w[d*Rc];
            slv[r]=siluf_(s);
        }
        __syncthreads();

        // ---- Phase D stage 2 ----
        size_t tb32 = ((size_t)(h*Bq+b)*TT + t)*DKPc;
        size_t tb64 = ((size_t)(h*Bq+b)*TT + t)*DVc;
        if(tid<32){
            const float* w = alpha_down + (size_t)hekv*DAc*DKPc + tid;
            float s=0.f;
            #pragma unroll
            for(int a=0;a<DAc;a++) s += sam[a]*w[a*DKPc];
            g_a[tb32+tid]=sigmoidf_(s);
        }
        if(tid==32){
            const float* w = beta_down + (size_t)hekv*DAc;
            float s=0.f;
            #pragma unroll
            for(int a=0;a<DAc;a++) s += sbm[a]*w[a];
            g_be[(size_t)(h*Bq+b)*TT+t]=sigmoidf_(s);
        }
        if(tid>=64 && tid<80){
            int k=tid-64;
            const float* w = lora_B_k + (size_t)hekv*Rc*DKc + k;
            float s=skraw[k];
            #pragma unroll
            for(int r=0;r<Rc;r++) s += slk[r]*w[r*DKc];
            skvec[k]=s;
        }
        if(tid>=128 && tid<192){
            int e=tid-128;
            const float* w = lora_B_v + (size_t)hekv*Rc*DVc + e;
            float s=svraw[e];
            #pragma unroll
            for(int r=0;r<Rc;r++) s += slv[r]*w[r*DVc];
            g_v[tb64+e]=siluf_(s);
        }
        __syncthreads();

        // ---- Phase D stage 3: k l2norm + PoPE ----
        if(wid==0){
            float val=(lane<16)? skvec[lane] : 0.f;
            float ss=val*val;
            #pragma unroll
            for(int o=8;o;o>>=1) ss += __shfl_xor_sync(0xffffffffu, ss, o);
            if(lane<16){
                float nrm=sqrtf(ss);
                float x=val/fmaxf(nrm,1e-12f);
                float mu=softplusf_(x);
                float ph=(float)t*sfreq[lane]-sshift[lane];
                g_k[tb32+lane]    = mu*cosf(ph);
                g_k[tb32+16+lane] = mu*sinf(ph);
            }
        }
        __syncthreads();

        // ---- Phase E: Q path (expert 0 is a no-op for Q) ----
        if(eq!=0){
            {
                float v=0.f;
                #pragma unroll
                for(int n=0;n<4;n++) v += sHq[n]*stream[(((b*NM+n)*TT)+t)*DD+tid];
                float tot = blockSum256(v*v, sred);
                float sc = rsqrtf(tot*(1.f/256.f)+1e-6f);
                she[tid]=v*sc*norm_w[heq*DD+tid];
            }
            __syncthreads();
            // stage1q
            for(int o=tid;o<DPGc;o+=256){
                const float* w = W_pg1 + (size_t)heq*DD*DPGc + o;
                float s=0.f;
                #pragma unroll 8
                for(int d=0;d<DD;d++) s += she[d]*w[(size_t)d*DPGc];
                smid[o]=siluf_(s);
            }
            if(tid<16){
                const float* w = Wq + (size_t)h*DD*DKc + tid;
                float s=0.f;
                #pragma unroll 8
                for(int d=0;d<DD;d++) s += she[d]*w[d*DKc];
                skraw[tid]=s;
            }
            if(tid>=32 && tid<36){
                int r=tid-32;
                const float* w = lora_A_q + (size_t)heq*DD*Rc + r;
                float s=0.f;
                #pragma unroll 8
                for(int d=0;d<DD;d++) s += she[d]*w[d*Rc];
                slk[r]=siluf_(s);
            }
            __syncthreads();
            // stage2q
            {
                const float* w = W_pg2 + (size_t)heq*DPGc*DD + tid;
                float s=0.f;
                for(int p=0;p<DPGc;p++) s += smid[p]*w[(size_t)p*DD];
                sacc_post[tid] += sigmoidf_(s)*0.125f;
            }
            if(tid>=64 && tid<80){
                int k=tid-64;
                const float* w = lora_B_q + (size_t)heq*Rc*DKc + k;
                float s=skraw[k];
                #pragma unroll
                for(int r=0;r<Rc;r++) s += slk[r]*w[r*DKc];
                skvec[k]=s;
            }
            __syncthreads();
            // stage3q
            if(wid==0){
                float val=(lane<16)? skvec[lane] : 0.f;
                float ss=val*val;
                #pragma unroll
                for(int o=8;o;o>>=1) ss += __shfl_xor_sync(0xffffffffu, ss, o);
                if(lane<16){
                    float nrm=sqrtf(ss);
                    float x=val/fmaxf(nrm,1e-12f);
                    float mu=softplusf_(x);
                    float ph=(float)t*sfreq[lane];
                    g_q[tb32+lane]    = mu*cosf(ph);
                    g_q[tb32+16+lane] = mu*sinf(ph);
                }
            }
        } else {
            if(tid<32) g_q[tb32+tid]=0.f;
        }
        __syncthreads();
    } // h loop

    for(int o=tid;o<DATTNc;o+=256) g_accpre[(size_t)bt*DATTNc+o]=sacc_pre[o];
    g_accpost[(size_t)bt*DD+tid]=sacc_post[tid];
    if(tid<16) g_accres[bt*16+tid]=sacc_res[tid];
    if(tid<4)  g_acchp [bt*4+tid]=sacc_hp[tid];
}

// ---------------- kernel 4: KDA delta-rule recurrence ----------------
__global__ void k_rec(){
    int hb=blockIdx.x;       // h*Bq + b
    int e=threadIdx.x;       // 0..63 (DV column)
    __shared__ float sq[32], sk[32], sa[32], sv[64], sb[1];
    float S[32];
    #pragma unroll
    for(int d=0;d<32;d++) S[d]=0.f;
    size_t b32=(size_t)hb*TT*DKPc, b64=(size_t)hb*TT*DVc;
    for(int t=0;t<TT;t++){
        __syncthreads();
        if(e<32){ sq[e]=g_q[b32+t*32+e]; sk[e]=g_k[b32+t*32+e]; sa[e]=g_a[b32+t*32+e]; }
        sv[e]=g_v[b64+t*64+e];
        if(e==63) sb[0]=g_be[(size_t)hb*TT+t];
        __syncthreads();
        float k0=0,k1=0,k2=0,k3=0;
        #pragma unroll
        for(int d=0;d<32;d+=4){
            k0+=sk[d+0]*(sa[d+0]*S[d+0]);
            k1+=sk[d+1]*(sa[d+1]*S[d+1]);
            k2+=sk[d+2]*(sa[d+2]*S[d+2]);
            k3+=sk[d+3]*(sa[d+3]*S[d+3]);
        }
        float kaS=(k0+k1)+(k2+k3);
        float w=sb[0]*(sv[e]-kaS);
        float o0=0,o1=0,o2=0,o3=0;
        #pragma unroll
        for(int d=0;d<32;d+=4){
            S[d+0]=sa[d+0]*S[d+0]+sk[d+0]*w; o0+=sq[d+0]*S[d+0];
            S[d+1]=sa[d+1]*S[d+1]+sk[d+1]*w; o1+=sq[d+1]*S[d+1];
            S[d+2]=sa[d+2]*S[d+2]+sk[d+2]*w; o2+=sq[d+2]*S[d+2];
            S[d+3]=sa[d+3]*S[d+3]+sk[d+3]*w; o3+=sq[d+3]*S[d+3];
        }
        g_o[b64+t*64+e]=(o0+o1)+(o2+o3);
    }
}

// ---------------- kernel 5: result = (concat*acc_pre)@W_o * acc_post ----------------
__global__ void k_result(const float* __restrict__ W_o){
    int bt=blockIdx.x, tid=threadIdx.x;
    int b=bt>>10, t=bt&1023;
    __shared__ float g[DATTNc];
    for(int c=tid;c<DATTNc;c+=256){
        int hh=c>>6, e=c&63;
        float ov = (g_qsel[hh*BT+bt]==0) ? 0.f
                 : g_o[((size_t)(hh*Bq+b)*TT + t)*DVc + e];
        g[c] = (ov/22.627416997969522f) * g_accpre[(size_t)bt*DATTNc+c];
    }
    __syncthreads();
    float s=0.f;
    #pragma unroll 8
    for(int c=0;c<DATTNc;c++) s += g[c]*W_o[(size_t)c*DD+tid];
    g_res[(size_t)bt*DD+tid] = s * g_accpost[(size_t)bt*DD+tid];
}

// ---------------- kernel 6: final stream mixing ----------------
__global__ void k_final(const float* __restrict__ stream, float* __restrict__ out){
    int bt=blockIdx.x, tid=threadIdx.x;
    int b=bt>>10, t=bt&1023;
    __shared__ float sres[16], shp[4];
    if(tid<16) sres[tid]=g_accres[bt*16+tid]*0.125f;
    if(tid<4)  shp[tid] =g_acchp [bt*4+tid]*0.125f;
    __syncthreads();
    float r=g_res[(size_t)bt*DD+tid];
    float st[4];
    #pragma unroll
    for(int j=0;j<4;j++) st[j]=stream[(((b*NM+j)*TT)+t)*DD+tid];
    #pragma unroll
    for(int n=0;n<4;n++){
        float acc = sres[n*4+0]*st[0]+sres[n*4+1]*st[1]+sres[n*4+2]*st[2]+sres[n*4+3]*st[3];
        acc += shp[n]*r;
        out[(((b*NM+n)*TT)+t)*DD+tid]=acc;
    }
}

// ---------------- launch ----------------
extern "C" void kernel_launch(void* const* d_in, const int* in_sizes, int n_in,
                              void* d_out, int out_size){
    const float* stream     =(const float*)d_in[0];
    const float* Wq         =(const float*)d_in[1];
    const float* Wk         =(const float*)d_in[2];
    const float* Wv         =(const float*)d_in[3];
    const float* pope_delta =(const float*)d_in[4];
    const float* q_router   =(const float*)d_in[5];
    const float* kv_router  =(const float*)d_in[6];
    const float* lora_A_q   =(const float*)d_in[7];
    const float* lora_B_q   =(const float*)d_in[8];
    const float* lora_A_k   =(const float*)d_in[9];
    const float* lora_B_k   =(const float*)d_in[10];
    const float* lora_A_v   =(const float*)d_in[11];
    const float* lora_B_v   =(const float*)d_in[12];
    const float* alpha_up   =(const float*)d_in[13];
    const float* alpha_down =(const float*)d_in[14];
    const float* beta_up    =(const float*)d_in[15];
    const float* beta_down  =(const float*)d_in[16];
    const float* mhc_norm_w =(const float*)d_in[17];
    const float* phi_pre    =(const float*)d_in[18];
    const float* phi_post   =(const float*)d_in[19];
    const float* phi_res    =(const float*)d_in[20];
    const float* b_pre      =(const float*)d_in[21];
    const float* b_post     =(const float*)d_in[22];
    const float* b_res      =(const float*)d_in[23];
    const float* a_pre      =(const float*)d_in[24];
    const float* a_post     =(const float*)d_in[25];
    const float* a_res      =(const float*)d_in[26];
    const float* norm_w     =(const float*)d_in[27];
    const float* W_pre      =(const float*)d_in[28];
    const float* W_o        =(const float*)d_in[29];
    const float* W_pg1      =(const float*)d_in[30];
    const float* W_pg2      =(const float*)d_in[31];

    k_prep <<<BT,256>>>(stream);
    k_route<<<BT,256>>>(q_router, kv_router);
    k_main <<<BT,256>>>(stream, Wq, Wk, Wv, pope_delta,
                        lora_A_q, lora_B_q, lora_A_k, lora_B_k, lora_A_v, lora_B_v,
                        alpha_up, alpha_down, beta_up, beta_down,
                        mhc_norm_w, phi_pre, phi_post, phi_res,
                        b_pre, b_post, b_res, a_pre, a_post, a_res,
                        norm_w, W_pre, W_pg1, W_pg2);
    k_rec  <<<Hc*Bq,64>>>();
    k_result<<<BT,256>>>(W_o);
    k_final <<<BT,256>>>(stream, (float*)d_out);
}

// round 2
// speedup vs baseline: 1.8781x; 1.8781x over previous
#include <cuda_runtime.h>
#include <math.h>

// ---------------- problem dims ----------------
#define Bq    4
#define NM    4
#define TT    1024
#define DD    256
#define DKc   16
#define DVc   64
#define DKPc  32
#define Hc    8
#define Ec    4
#define HEc   32
#define Rc    4
#define DAc   25
#define DPGc  316
#define NDc   1024
#define DATTNc 512
#define BT    (Bq*TT)   // 4096

// ---------------- scratch (device globals) ----------------
__device__ float g_xhat [BT*NDc];
__device__ float g_route[BT*DD];
__device__ int   g_qsel [Hc*BT];
__device__ int   g_kvsel[Hc*BT];
__device__ int   g_kvcnt[32];
__device__ int   g_qcnt [32];
__device__ int   g_kvlist[32*BT];
__device__ int   g_qlist [32*BT];
__device__ float g_hekv[(size_t)Hc*BT*DD];    // he for kv expert
__device__ float g_heq [(size_t)Hc*BT*DD];    // he for q expert (only q-listed)
__device__ float g_preh[(size_t)Hc*BT*DATTNc];// silu(W_pre)*0.125 per h
__device__ float g_posth[(size_t)Hc*BT*DD];   // sigmoid(pg2)*0.125 per h (zero if eq==0)
__device__ float g_pgmid[(size_t)Hc*BT*DPGc]; // silu(pg1) for q-listed
__device__ float g_vk  [(size_t)Hc*BT*80];    // [Wv(64) | Wk(16)] raw
__device__ float g_mid [(size_t)Hc*BT*64];    // silu([aup25|bup25|lAk4|lAv4]) padded
__device__ float g_q [Hc*BT*DKPc];
__device__ float g_k [Hc*BT*DKPc];
__device__ float g_a [Hc*BT*DKPc];
__device__ float g_v [Hc*BT*DVc];
__device__ float g_be[Hc*BT];
__device__ float g_accres [BT*16];
__device__ float g_acchp  [BT*4];
__device__ float g_o  [Hc*BT*DVc];
__device__ float g_res[BT*DD];
__device__ float g_frq[16];
__device__ float g_shf[16];

// ---------------- helpers ----------------
__device__ __forceinline__ float sigmoidf_(float x){ return 1.f/(1.f+expf(-x)); }
__device__ __forceinline__ float siluf_(float x){ return x/(1.f+expf(-x)); }
__device__ __forceinline__ float softplusf_(float x){ return fmaxf(x,0.f)+log1pf(expf(-fabsf(x))); }

__device__ __forceinline__ float warpSum(float v){
    #pragma unroll
    for(int o=16;o;o>>=1) v += __shfl_xor_sync(0xffffffffu, v, o);
    return v;
}
__device__ __forceinline__ float blockSum256(float v, float* sred){
    int lane=threadIdx.x&31, wid=threadIdx.x>>5;
    v = warpSum(v);
    if(lane==0) sred[wid]=v;
    __syncthreads();
    if(wid==0){
        float x = (lane<8)? sred[lane] : 0.f;
        x = warpSum(x);
        if(lane==0) sred[0]=x;
    }
    __syncthreads();
    float r = sred[0];
    __syncthreads();
    return r;
}

template<int ACT> __device__ __forceinline__ float actf(float x){
    if(ACT==0) return siluf_(x)*0.125f;
    if(ACT==1) return siluf_(x);
    if(ACT==2) return sigmoidf_(x)*0.125f;
    return x;
}

// ---------------- kernel 0: zero counters ----------------
__global__ void k_zero(){
    int t=threadIdx.x;
    if(t<32){ g_kvcnt[t]=0; g_qcnt[t]=0; }
}

// ---------------- kernel 1: x_hat + route_in + pope constants ----------------
__global__ void k_prep(const float* __restrict__ stream, const float* __restrict__ pope_delta){
    int bt=blockIdx.x, tid=threadIdx.x;
    int b=bt>>10, t=bt&1023;
    __shared__ float sred[8];
    float v[NM]; float ss=0.f;
    #pragma unroll
    for(int n=0;n<NM;n++){
        v[n]=stream[(((b*NM+n)*TT)+t)*DD+tid];
        ss += v[n]*v[n];
    }
    float tot = blockSum256(ss, sred);
    float scale = rsqrtf(tot*(1.f/1024.f) + 1e-6f);
    #pragma unroll
    for(int n=0;n<NM;n++) g_xhat[(size_t)bt*NDc + n*DD + tid] = v[n]*scale;
    g_route[bt*DD+tid] = (v[0]+v[1]+v[2]+v[3])*0.25f;
    if(bt==0 && tid<16){
        g_frq[tid] = (float)pow(10000.0, ((double)tid)/16.0);
        g_shf[tid] = 6.283185307179586f * sigmoidf_(pope_delta[tid]);
    }
}

// ---------------- kernel 2: routing + token lists ----------------
__global__ void k_route(const float* __restrict__ q_router, const float* __restrict__ kv_router){
    int bt=blockIdx.x; int tid=threadIdx.x; int lane=tid&31, h=tid>>5;
    __shared__ float r[DD];
    r[tid]=g_route[bt*DD+tid];
    __syncthreads();
    float aq[4]={0,0,0,0}, ak[4]={0,0,0,0};
    for(int d=lane; d<DD; d+=32){
        float x=r[d];
        const float* wq=q_router + (h*DD+d)*Ec;
        const float* wk=kv_router+ (h*DD+d)*Ec;
        #pragma unroll
        for(int e=0;e<4;e++){ aq[e]+=x*wq[e]; ak[e]+=x*wk[e]; }
    }
    #pragma unroll
    for(int e=0;e<4;e++){ aq[e]=warpSum(aq[e]); ak[e]=warpSum(ak[e]); }
    if(lane==0){
        int bqi=0; float bv=fminf(fmaxf(aq[0],-10.f),10.f);
        #pragma unroll
        for(int e=1;e<4;e++){ float c=fminf(fmaxf(aq[e],-10.f),10.f); if(c>bv){bv=c;bqi=e;} }
        int bki=0; float kvb=fminf(fmaxf(ak[0],-10.f),10.f);
        #pragma unroll
        for(int e=1;e<4;e++){ float c=fminf(fmaxf(ak[e],-10.f),10.f); if(c>kvb){kvb=c;bki=e;} }
        g_qsel [h*BT+bt]=bqi;
        g_kvsel[h*BT+bt]=bki;
        int p=atomicAdd(&g_kvcnt[h*4+bki],1);
        g_kvlist[(h*4+bki)*BT+p]=bt;
        if(bqi!=0){
            int p2=atomicAdd(&g_qcnt[h*4+bqi],1);
            g_qlist[(h*4+bqi)*BT+p2]=bt;
        }
    }
}

// ---------------- kernel 3: per-token main (dots, sinkhorn, he, q small path) ----------------
__global__ void __launch_bounds__(256) k_main(
    const float* __restrict__ stream,
    const float* __restrict__ Wq,
    const float* __restrict__ lora_A_q, const float* __restrict__ lora_B_q,
    const float* __restrict__ mhc_norm_w,
    const float* __restrict__ phi_pre, const float* __restrict__ phi_post, const float* __restrict__ phi_res,
    const float* __restrict__ b_pre, const float* __restrict__ b_post, const float* __restrict__ b_res,
    const float* __restrict__ a_pre, const float* __restrict__ a_post, const float* __restrict__ a_res,
    const float* __restrict__ norm_w)
{
    int bt=blockIdx.x, tid=threadIdx.x;
    int b=bt>>10, t=bt&1023;
    int lane=tid&31, wid=tid>>5;

    __shared__ float xh[NDc];
    __shared__ float sxk[NDc];
    __shared__ float sxq[NDc];
    __shared__ float she[DD];
    __shared__ float sdots[28];
    __shared__ float sHq[4], sHkv[4];
    __shared__ float skraw[16], slq[4], skvec[16];
    __shared__ float sacc_res[16];
    __shared__ float sacc_hp[4];
    __shared__ float sred[8];

    for(int i=tid;i<NDc;i+=256) xh[i]=g_xhat[(size_t)bt*NDc+i];
    if(tid<16) sacc_res[tid]=0.f;
    if(tid<4)  sacc_hp[tid]=0.f;
    __syncthreads();

    for(int h=0;h<Hc;h++){
        int eq  = g_qsel [h*BT+bt];
        int ekv = g_kvsel[h*BT+bt];
        int heq = h*Ec+eq, hekv = h*Ec+ekv;

        // fold norm weight
        for(int i=tid;i<NDc;i+=256){
            float x=xh[i];
            sxk[i]=x*mhc_norm_w[(size_t)hekv*NDc+i];
            sxq[i]=x*mhc_norm_w[(size_t)heq *NDc+i];
        }
        __syncthreads();

        // ---- Phase A: 28 length-1024 dots ----
        for(int j=wid;j<28;j+=8){
            const float* src; const float* phi; int stride;
            if(j<4)      { src=sxq; phi=phi_pre +(size_t)heq *NDc*4  + j;      stride=4; }
            else if(j<8) { src=sxk; phi=phi_pre +(size_t)hekv*NDc*4  + (j-4);  stride=4; }
            else if(j<12){ src=sxk; phi=phi_post+(size_t)hekv*NDc*4  + (j-8);  stride=4; }
            else         { src=sxk; phi=phi_res +(size_t)hekv*NDc*16 + (j-12); stride=16;}
            float s=0.f;
            for(int k=lane;k<NDc;k+=32) s += src[k]*phi[(size_t)k*stride];
            s = warpSum(s);
            if(lane==0) sdots[j]=s;
        }
        __syncthreads();

        // ---- Phase B: sigmoids + sinkhorn ----
        if(tid==0){
            float apq=a_pre[heq], apk=a_pre[hekv], apo=a_post[hekv], ars=a_res[hekv];
            #pragma unroll
            for(int n=0;n<4;n++){
                sHq [n] = sigmoidf_(apq*sdots[n]   + b_pre[heq*4+n]);
                sHkv[n] = sigmoidf_(apk*sdots[4+n] + b_pre[hekv*4+n]);
                sacc_hp[n] += 2.f*sigmoidf_(apo*sdots[8+n] + b_post[hekv*4+n]);
            }
            float M[16];
            #pragma unroll
            for(int m=0;m<16;m++) M[m]=expf(ars*sdots[12+m] + b_res[hekv*16+m]);
            #pragma unroll
            for(int it=0;it<6;it++){
                #pragma unroll
                for(int i=0;i<4;i++){ float s=M[i*4]+M[i*4+1]+M[i*4+2]+M[i*4+3];
                    M[i*4]/=s; M[i*4+1]/=s; M[i*4+2]/=s; M[i*4+3]/=s; }
                #pragma unroll
                for(int j=0;j<4;j++){ float s=M[j]+M[4+j]+M[8+j]+M[12+j];
                    M[j]/=s; M[4+j]/=s; M[8+j]/=s; M[12+j]/=s; }
            }
            #pragma unroll
            for(int m=0;m<16;m++) sacc_res[m]+=M[m];
        }
        __syncthreads();

        // ---- Phase C: he for kv expert ----
        {
            float v=0.f;
            #pragma unroll
            for(int n=0;n<4;n++) v += sHkv[n]*stream[(((b*NM+n)*TT)+t)*DD+tid];
            float tot = blockSum256(v*v, sred);
            float sc = rsqrtf(tot*(1.f/256.f)+1e-6f);
            g_hekv[((size_t)h*BT+bt)*DD+tid] = v*sc*norm_w[hekv*DD+tid];
        }

        // ---- Phase E: Q path ----
        if(eq!=0){
            {
                float v=0.f;
                #pragma unroll
                for(int n=0;n<4;n++) v += sHq[n]*stream[(((b*NM+n)*TT)+t)*DD+tid];
                float tot = blockSum256(v*v, sred);
                float sc = rsqrtf(tot*(1.f/256.f)+1e-6f);
                float hv = v*sc*norm_w[heq*DD+tid];
                she[tid]=hv;
                g_heq[((size_t)h*BT+bt)*DD+tid]=hv;
            }
            __syncthreads();
            if(tid<16){
                const float* w = Wq + (size_t)h*DD*DKc + tid;
                float s=0.f;
                #pragma unroll 8
                for(int d=0;d<DD;d++) s += she[d]*w[d*DKc];
                skraw[tid]=s;
            }
            if(tid>=32 && tid<36){
                int r=tid-32;
                const float* w = lora_A_q + (size_t)heq*DD*Rc + r;
                float s=0.f;
                #pragma unroll 8
                for(int d=0;d<DD;d++) s += she[d]*w[d*Rc];
                slq[r]=siluf_(s);
            }
            __syncthreads();
            if(tid>=64 && tid<80){
                int k=tid-64;
                const float* w = lora_B_q + (size_t)heq*Rc*DKc + k;
                float s=skraw[k];
                #pragma unroll
                for(int r=0;r<Rc;r++) s += slq[r]*w[r*DKc];
                skvec[k]=s;
            }
            __syncthreads();
            if(wid==0){
                float val=(lane<16)? skvec[lane] : 0.f;
                float ss=val*val;
                #pragma unroll
                for(int o=8;o;o>>=1) ss += __shfl_xor_sync(0xffffffffu, ss, o);
                if(lane<16){
                    float nrm=sqrtf(ss);
                    float x=val/fmaxf(nrm,1e-12f);
                    float mu=softplusf_(x);
                    float ph=(float)t*g_frq[lane];
                    size_t tb32=((size_t)h*BT+bt)*DKPc;
                    g_q[tb32+lane]    = mu*cosf(ph);
                    g_q[tb32+16+lane] = mu*sinf(ph);
                }
            }
        } else {
            if(tid<32) g_q[((size_t)h*BT+bt)*DKPc+tid]=0.f;
            g_posth[((size_t)h*BT+bt)*DD+tid]=0.f;
        }
        __syncthreads();
    } // h loop

    if(tid<16) g_accres[bt*16+tid]=sacc_res[tid];
    if(tid<4)  g_acchp [bt*4+tid]=sacc_hp[tid];
}

// ---------------- grouped GEMM (gathered A rows) ----------------
template<int KDIM,int NDIM,int ACT>
__global__ void __launch_bounds__(256) k_ggemm(
    const float* __restrict__ Ab, const float* __restrict__ Bb, float* __restrict__ Ob,
    const int* __restrict__ cnts, const int* __restrict__ lists)
{
    int g = blockIdx.z;
    int cnt = cnts[g];
    int m0 = blockIdx.x*64;
    if(m0>=cnt) return;
    int h = g>>2;
    int n0 = blockIdx.y*64;
    int tid=threadIdx.x;

    __shared__ int stok[64];
    __shared__ float As[16][68];
    __shared__ float Bs[16][68];

    if(tid<64){ int m=m0+tid; stok[tid]=(m<cnt)? lists[g*BT+m] : -1; }
    __syncthreads();

    int am=tid>>2, akq=tid&3;
    int atok=stok[am];
    const float* arow = Ab + ((size_t)h*BT + (atok<0?0:atok))*KDIM;
    const float* Bg = Bb + (size_t)g*KDIM*NDIM;
    int bkk=tid>>4, bnq=tid&15;
    int tm0=(tid&15)*4, tn0=(tid>>4)*4;

    float acc[4][4]={};
    for(int k0=0;k0<KDIM;k0+=16){
        int ak=k0+akq*4;
        float4 av=make_float4(0,0,0,0);
        if(atok>=0 && ak<KDIM) av=*(const float4*)(arow+ak);
        As[akq*4+0][am]=av.x; As[akq*4+1][am]=av.y;
        As[akq*4+2][am]=av.z; As[akq*4+3][am]=av.w;
        int bk=k0+bkk, bn=n0+bnq*4;
        float4 bv=make_float4(0,0,0,0);
        if(bk<KDIM && bn<NDIM) bv=*(const float4*)(Bg+(size_t)bk*NDIM+bn);
        *(float4*)&Bs[bkk][bnq*4]=bv;
        __syncthreads();
        #pragma unroll
        for(int kk=0;kk<16;kk++){
            float4 a=*(float4*)&As[kk][tm0];
            float4 bb_=*(float4*)&Bs[kk][tn0];
            acc[0][0]+=a.x*bb_.x; acc[0][1]+=a.x*bb_.y; acc[0][2]+=a.x*bb_.z; acc[0][3]+=a.x*bb_.w;
            acc[1][0]+=a.y*bb_.x; acc[1][1]+=a.y*bb_.y; acc[1][2]+=a.y*bb_.z; acc[1][3]+=a.y*bb_.w;
            acc[2][0]+=a.z*bb_.x; acc[2][1]+=a.z*bb_.y; acc[2][2]+=a.z*bb_.z; acc[2][3]+=a.z*bb_.w;
            acc[3][0]+=a.w*bb_.x; acc[3][1]+=a.w*bb_.y; acc[3][2]+=a.w*bb_.z; acc[3][3]+=a.w*bb_.w;
        }
        __syncthreads();
    }
    int nbase=n0+tn0;
    if(nbase<NDIM){
        #pragma unroll
        for(int i=0;i<4;i++){
            int tok=stok[tm0+i];
            if(tok>=0){
                float4 r;
                r.x=actf<ACT>(acc[i][0]); r.y=actf<ACT>(acc[i][1]);
                r.z=actf<ACT>(acc[i][2]); r.w=actf<ACT>(acc[i][3]);
                *(float4*)(Ob + ((size_t)h*BT+tok)*NDIM + nbase) = r;
            }
        }
    }
}

// ---------------- GEMM: [Wv|Wk] per head, all tokens ----------------
__global__ void __launch_bounds__(256) k_gemm_vk(
    const float* __restrict__ Wv, const float* __restrict__ Wk)
{
    int h = blockIdx.z;
    int m0 = blockIdx.x*64;
    int n0 = blockIdx.y*64;
    int tid=threadIdx.x;
    __shared__ float As[16][68];
    __shared__ float Bs[16][68];

    int am=tid>>2, akq=tid&3;
    const float* arow = g_hekv + ((size_t)h*BT + m0+am)*DD;
    int bkk=tid>>4, bnq=tid&15;
    int tm0=(tid&15)*4, tn0=(tid>>4)*4;

    float acc[4][4]={};
    for(int k0=0;k0<DD;k0+=16){
        int ak=k0+akq*4;
        float4 av=*(const float4*)(arow+ak);
        As[akq*4+0][am]=av.x; As[akq*4+1][am]=av.y;
        As[akq*4+2][am]=av.z; As[akq*4+3][am]=av.w;
        int bk=k0+bkk, bn=n0+bnq*4;
        float4 bv=make_float4(0,0,0,0);
        if(bn<64)      bv=*(const float4*)(Wv+(size_t)h*DD*64 + (size_t)bk*64 + bn);
        else if(bn<80) bv=*(const float4*)(Wk+(size_t)h*DD*16 + (size_t)bk*16 + (bn-64));
        *(float4*)&Bs[bkk][bnq*4]=bv;
        __syncthreads();
        #pragma unroll
        for(int kk=0;kk<16;kk++){
            float4 a=*(float4*)&As[kk][tm0];
            float4 bb_=*(float4*)&Bs[kk][tn0];
            acc[0][0]+=a.x*bb_.x; acc[0][1]+=a.x*bb_.y; acc[0][2]+=a.x*bb_.z; acc[0][3]+=a.x*bb_.w;
            acc[1][0]+=a.y*bb_.x; acc[1][1]+=a.y*bb_.y; acc[1][2]+=a.y*bb_.z; acc[1][3]+=a.y*bb_.w;
            acc[2][0]+=a.z*bb_.x; acc[2][1]+=a.z*bb_.y; acc[2][2]+=a.z*bb_.z; acc[2][3]+=a.z*bb_.w;
            acc[3][0]+=a.w*bb_.x; acc[3][1]+=a.w*bb_.y; acc[3][2]+=a.w*bb_.z; acc[3][3]+=a.w*bb_.w;
        }
        __syncthreads();
    }
    int nbase=n0+tn0;
    if(nbase<80){
        #pragma unroll
        for(int i=0;i<4;i++){
            float4 r=make_float4(acc[i][0],acc[i][1],acc[i][2],acc[i][3]);
            *(float4*)(g_vk + ((size_t)h*BT + m0+tm0+i)*80 + nbase) = r;
        }
    }
}

// ---------------- GEMM: fused [alpha_up|beta_up|loraAk|loraAv] per (h,e) group ----------------
__global__ void __launch_bounds__(256) k_gemm_mid(
    const float* __restrict__ alpha_up, const float* __restrict__ beta_up,
    const float* __restrict__ lora_A_k, const float* __restrict__ lora_A_v)
{
    int g = blockIdx.z;
    int cnt = g_kvcnt[g];
    int m0 = blockIdx.x*64;
    if(m0>=cnt) return;
    int h = g>>2;
    int tid=threadIdx.x;
    __shared__ int stok[64];
    __shared__ float As[16][68];
    __shared__ float Bs[16][68];

    if(tid<64){ int m=m0+tid; stok[tid]=(m<cnt)? g_kvlist[g*BT+m] : -1; }
    __syncthreads();

    int am=tid>>2, akq=tid&3;
    int atok=stok[am];
    const float* arow = g_hekv + ((size_t)h*BT + (atok<0?0:atok))*DD;
    int tm0=(tid&15)*4, tn0=(tid>>4)*4;
    int bn=tid&63, bkb=tid>>6;

    float acc[4][4]={};
    for(int k0=0;k0<DD;k0+=16){
        int ak=k0+akq*4;
        float4 av=make_float4(0,0,0,0);
        if(atok>=0) av=*(const float4*)(arow+ak);
        As[akq*4+0][am]=av.x; As[akq*4+1][am]=av.y;
        As[akq*4+2][am]=av.z; As[akq*4+3][am]=av.w;
        #pragma unroll
        for(int p=0;p<4;p++){
            int kk=bkb+4*p;
            int k=k0+kk;
            float bval=0.f;
            if(bn<25)       bval=alpha_up [(size_t)g*DD*DAc + (size_t)k*DAc + bn];
            else if(bn<50)  bval=beta_up  [(size_t)g*DD*DAc + (size_t)k*DAc + (bn-25)];
            else if(bn<54)  bval=lora_A_k [(size_t)g*DD*Rc  + (size_t)k*Rc  + (bn-50)];
            else if(bn<58)  bval=lora_A_v [(size_t)g*DD*Rc  + (size_t)k*Rc  + (bn-54)];
            Bs[kk][bn]=bval;
        }
        __syncthreads();
        #pragma unroll
        for(int kk=0;kk<16;kk++){
            float4 a=*(float4*)&As[kk][tm0];
            float4 bb_=*(float4*)&Bs[kk][tn0];
            acc[0][0]+=a.x*bb_.x; acc[0][1]+=a.x*bb_.y; acc[0][2]+=a.x*bb_.z; acc[0][3]+=a.x*bb_.w;
            acc[1][0]+=a.y*bb_.x; acc[1][1]+=a.y*bb_.y; acc[1][2]+=a.y*bb_.z; acc[1][3]+=a.y*bb_.w;
            acc[2][0]+=a.z*bb_.x; acc[2][1]+=a.z*bb_.y; acc[2][2]+=a.z*bb_.z; acc[2][3]+=a.z*bb_.w;
            acc[3][0]+=a.w*bb_.x; acc[3][1]+=a.w*bb_.y; acc[3][2]+=a.w*bb_.z; acc[3][3]+=a.w*bb_.w;
        }
        __syncthreads();
    }
    #pragma unroll
    for(int i=0;i<4;i++){
        int tok=stok[tm0+i];
        if(tok>=0){
            float4 r;
            r.x=siluf_(acc[i][0]); r.y=siluf_(acc[i][1]);
            r.z=siluf_(acc[i][2]); r.w=siluf_(acc[i][3]);
            *(float4*)(g_mid + ((size_t)h*BT+tok)*64 + tn0) = r;
        }
    }
}

// ---------------- kernel: finish kv path (alpha_down, beta_down, loraB, k-pope, v) ----------------
__global__ void __launch_bounds__(64) k_finish(
    const float* __restrict__ alpha_down, const float* __restrict__ beta_down,
    const float* __restrict__ lora_B_k, const float* __restrict__ lora_B_v)
{
    int bt=blockIdx.x, h=blockIdx.y;
    int tid=threadIdx.x;
    int t=bt&1023;
    int ekv=g_kvsel[h*BT+bt];
    int g=h*4+ekv;
    __shared__ float mid[64];
    __shared__ float skv[16];
    size_t row=(size_t)h*BT+bt;
    mid[tid]=g_mid[row*64+tid];
    __syncthreads();

    // v = silu(vk + loraBv)
    {
        float s = g_vk[row*80+tid];
        const float* w = lora_B_v + (size_t)g*Rc*DVc + tid;
        #pragma unroll
        for(int r=0;r<Rc;r++) s += mid[54+r]*w[r*DVc];
        g_v[row*DVc+tid]=siluf_(s);
    }
    if(tid<32){
        const float* w = alpha_down + (size_t)g*DAc*DKPc + tid;
        float s=0.f;
        #pragma unroll
        for(int a=0;a<DAc;a++) s += mid[a]*w[a*DKPc];
        g_a[row*DKPc+tid]=sigmoidf_(s);
    } else if(tid==32){
        const float* w = beta_down + (size_t)g*DAc;
        float s=0.f;
        #pragma unroll
        for(int a=0;a<DAc;a++) s += mid[25+a]*w[a];
        g_be[row]=sigmoidf_(s);
    } else if(tid>=40 && tid<56){
        int k=tid-40;
        float s = g_vk[row*80+64+k];
        const float* w = lora_B_k + (size_t)g*Rc*DKc + k;
        #pragma unroll
        for(int r=0;r<Rc;r++) s += mid[50+r]*w[r*DKc];
        skv[k]=s;
    }
    __syncthreads();
    if(tid<32){
        float val=(tid<16)? skv[tid] : 0.f;
        float ss=val*val;
        #pragma unroll
        for(int o=8;o;o>>=1) ss += __shfl_xor_sync(0xffffffffu, ss, o);
        if(tid<16){
            float nrm=sqrtf(ss);
            float x=val/fmaxf(nrm,1e-12f);
            float mu=softplusf_(x);
            float ph=(float)t*g_frq[tid]-g_shf[tid];
            g_k[row*DKPc+tid]    = mu*cosf(ph);
            g_k[row*DKPc+16+tid] = mu*sinf(ph);
        }
    }
}

// ---------------- kernel: KDA recurrence (warp per output column) ----------------
__global__ void __launch_bounds__(128) k_rec(){
    int hb = blockIdx.x;            // 0..31 (h*4+b)
    int warp = threadIdx.x>>5;
    int lane = threadIdx.x&31;
    int e = blockIdx.y*4 + warp;    // 0..63
    size_t b32=(size_t)hb*TT*DKPc, b64=(size_t)hb*TT*DVc, bb=(size_t)hb*TT;
    float S=0.f;
    float qc=g_q[b32+lane], kc=g_k[b32+lane], ac=g_a[b32+lane];
    float vc=g_v[b64+e], bec=g_be[bb];
    for(int t=0;t<TT;t++){
        float qn=0,kn=0,an=0,vn=0,ben=0;
        if(t+1<TT){
            size_t o32=b32+(size_t)(t+1)*DKPc;
            qn=g_q[o32+lane]; kn=g_k[o32+lane]; an=g_a[o32+lane];
            vn=g_v[b64+(size_t)(t+1)*DVc+e]; ben=g_be[bb+t+1];
        }
        float aS = ac*S;
        float p1 = kc*aS, p2=qc*aS, p3=qc*kc;
        #pragma unroll
        for(int o=16;o;o>>=1){
            p1 += __shfl_xor_sync(0xffffffffu,p1,o);
            p2 += __shfl_xor_sync(0xffffffffu,p2,o);
            p3 += __shfl_xor_sync(0xffffffffu,p3,o);
        }
        float w = bec*(vc-p1);
        S = aS + kc*w;
        float o_ = p2 + p3*w;
        if(lane==0) g_o[b64+(size_t)t*DVc+e]=o_;
        qc=qn;kc=kn;ac=an;vc=vn;bec=ben;
    }
}

// ---------------- kernel: result = (concat*acc_pre)@W_o * acc_post (16 tokens/block) ----------------
__global__ void __launch_bounds__(256) k_result(const float* __restrict__ W_o){
    int bt0=blockIdx.x*16, tid=threadIdx.x;
    __shared__ float A[16][512];
    for(int idx=tid; idx<16*512; idx+=256){
        int r=idx>>9, c=idx&511;
        int bt=bt0+r;
        int hh=c>>6;
        float accp=0.f;
        #pragma unroll
        for(int h2=0;h2<8;h2++) accp += g_preh[((size_t)h2*BT+bt)*DATTNc + c];
        float ov = (g_qsel[hh*BT+bt]==0)? 0.f : g_o[((size_t)hh*BT+bt)*DVc + (c&63)];
        A[r][c] = ov*(1.f/22.627416997969522f)*accp;
    }
    __syncthreads();
    float out[16];
    #pragma unroll
    for(int r=0;r<16;r++) out[r]=0.f;
    for(int c=0;c<512;c+=4){
        float w0=W_o[(size_t)c*DD+tid];
        float w1=W_o[(size_t)(c+1)*DD+tid];
        float w2=W_o[(size_t)(c+2)*DD+tid];
        float w3=W_o[(size_t)(c+3)*DD+tid];
        #pragma unroll
        for(int r=0;r<16;r++){
            float4 a=*(float4*)&A[r][c];
            out[r]+=a.x*w0+a.y*w1+a.z*w2+a.w*w3;
        }
    }
    #pragma unroll
    for(int r=0;r<16;r++){
        int bt=bt0+r;
        float ap=0.f;
        #pragma unroll
        for(int h2=0;h2<8;h2++) ap += g_posth[((size_t)h2*BT+bt)*DD+tid];
        g_res[(size_t)bt*DD+tid]=out[r]*ap;
    }
}

// ---------------- kernel: final stream mixing ----------------
__global__ void k_final(const float* __restrict__ stream, float* __restrict__ out){
    int bt=blockIdx.x, tid=threadIdx.x;
    int b=bt>>10, t=bt&1023;
    __shared__ float sres[16], shp[4];
    if(tid<16) sres[tid]=g_accres[bt*16+tid]*0.125f;
    if(tid<4)  shp[tid] =g_acchp [bt*4+tid]*0.125f;
    __syncthreads();
    float r=g_res[(size_t)bt*DD+tid];
    float st[4];
    #pragma unroll
    for(int j=0;j<4;j++) st[j]=stream[(((b*NM+j)*TT)+t)*DD+tid];
    #pragma unroll
    for(int n=0;n<4;n++){
        float acc = sres[n*4+0]*st[0]+sres[n*4+1]*st[1]+sres[n*4+2]*st[2]+sres[n*4+3]*st[3];
        acc += shp[n]*r;
        out[(((b*NM+n)*TT)+t)*DD+tid]=acc;
    }
}

// ---------------- launch ----------------
extern "C" void kernel_launch(void* const* d_in, const int* in_sizes, int n_in,
                              void* d_out, int out_size){
    const float* stream     =(const float*)d_in[0];
    const float* Wq         =(const float*)d_in[1];
    const float* Wk         =(const float*)d_in[2];
    const float* Wv         =(const float*)d_in[3];
    const float* pope_delta =(const float*)d_in[4];
    const float* q_router   =(const float*)d_in[5];
    const float* kv_router  =(const float*)d_in[6];
    const float* lora_A_q   =(const float*)d_in[7];
    const float* lora_B_q   =(const float*)d_in[8];
    const float* lora_A_k   =(const float*)d_in[9];
    const float* lora_B_k   =(const float*)d_in[10];
    const float* lora_A_v   =(const float*)d_in[11];
    const float* lora_B_v   =(const float*)d_in[12];
    const float* alpha_up   =(const float*)d_in[13];
    const float* alpha_down =(const float*)d_in[14];
    const float* beta_up    =(const float*)d_in[15];
    const float* beta_down  =(const float*)d_in[16];
    const float* mhc_norm_w =(const float*)d_in[17];
    const float* phi_pre    =(const float*)d_in[18];
    const float* phi_post   =(const float*)d_in[19];
    const float* phi_res    =(const float*)d_in[20];
    const float* b_pre      =(const float*)d_in[21];
    const float* b_post     =(const float*)d_in[22];
    const float* b_res      =(const float*)d_in[23];
    const float* a_pre      =(const float*)d_in[24];
    const float* a_post     =(const float*)d_in[25];
    const float* a_res      =(const float*)d_in[26];
    const float* norm_w     =(const float*)d_in[27];
    const float* W_pre      =(const float*)d_in[28];
    const float* W_o        =(const float*)d_in[29];
    const float* W_pg1      =(const float*)d_in[30];
    const float* W_pg2      =(const float*)d_in[31];

    int* kvcnt_p; cudaGetSymbolAddress((void**)&kvcnt_p, g_kvcnt);
    int* qcnt_p;  cudaGetSymbolAddress((void**)&qcnt_p,  g_qcnt);
    int* kvlist_p;cudaGetSymbolAddress((void**)&kvlist_p,g_kvlist);
    int* qlist_p; cudaGetSymbolAddress((void**)&qlist_p, g_qlist);
    float* hekv_p; cudaGetSymbolAddress((void**)&hekv_p, g_hekv);
    float* heq_p;  cudaGetSymbolAddress((void**)&heq_p,  g_heq);
    float* preh_p; cudaGetSymbolAddress((void**)&preh_p, g_preh);
    float* posth_p;cudaGetSymbolAddress((void**)&posth_p,g_posth);
    float* pgmid_p;cudaGetSymbolAddress((void**)&pgmid_p,g_pgmid);

    k_zero <<<1,64>>>();
    k_prep <<<BT,256>>>(stream, pope_delta);
    k_route<<<BT,256>>>(q_router, kv_router);
    k_main <<<BT,256>>>(stream, Wq, lora_A_q, lora_B_q,
                        mhc_norm_w, phi_pre, phi_post, phi_res,
                        b_pre, b_post, b_res, a_pre, a_post, a_res, norm_w);
    k_gemm_vk <<<dim3(64,2,8),256>>>(Wv, Wk);
    k_ggemm<256,512,0><<<dim3(64,8,32),256>>>(hekv_p, W_pre, preh_p, kvcnt_p, kvlist_p);
    k_gemm_mid<<<dim3(64,1,32),256>>>(alpha_up, beta_up, lora_A_k, lora_A_v);
    k_ggemm<256,316,1><<<dim3(64,5,32),256>>>(heq_p, W_pg1, pgmid_p, qcnt_p, qlist_p);
    k_ggemm<316,256,2><<<dim3(64,4,32),256>>>(pgmid_p, W_pg2, posth_p, qcnt_p, qlist_p);
    k_finish<<<dim3(BT,Hc),64>>>(alpha_down, beta_down, lora_B_k, lora_B_v);
    k_rec  <<<dim3(32,16),128>>>();
    k_result<<<256,256>>>(W_o);
    k_final <<<BT,256>>>(stream, (float*)d_out);
}

// round 3
// speedup vs baseline: 2.3005x; 1.2249x over previous
#include <cuda_runtime.h>
#include <math.h>

// ---------------- problem dims ----------------
#define Bq    4
#define NM    4
#define TT    1024
#define DD    256
#define DKc   16
#define DVc   64
#define DKPc  32
#define Hc    8
#define Ec    4
#define HEc   32
#define Rc    4
#define DAc   25
#define DPGc  316
#define NDc   1024
#define DATTNc 512
#define BT    (Bq*TT)   // 4096

// ---------------- scratch (device globals) ----------------
__device__ float g_xhat [BT*NDc];
__device__ float g_route[BT*DD];
__device__ int   g_qsel [Hc*BT];
__device__ int   g_kvsel[Hc*BT];
__device__ int   g_kvcnt[32];
__device__ int   g_qcnt [32];
__device__ int   g_kvlist[32*BT];
__device__ int   g_qlist [32*BT];
__device__ float g_bfold[(size_t)HEc*NDc*32];  // folded norm_w*phi tables
__device__ float g_dotkv[(size_t)Hc*BT*32];
__device__ float g_dotq [(size_t)Hc*BT*32];
__device__ float g_hekv[(size_t)Hc*BT*DD];
__device__ float g_heq [(size_t)Hc*BT*DD];
__device__ float g_preh[(size_t)Hc*BT*DATTNc];
__device__ float g_posth[(size_t)Hc*BT*DD];
__device__ float g_pgmid[(size_t)Hc*BT*DPGc];
__device__ float g_vk  [(size_t)Hc*BT*80];
__device__ float g_mid [(size_t)Hc*BT*64];
__device__ float g_q [Hc*BT*DKPc];
__device__ float g_k [Hc*BT*DKPc];
__device__ float g_a [Hc*BT*DKPc];
__device__ float g_v [Hc*BT*DVc];
__device__ float g_be[Hc*BT];
__device__ float g_accres [BT*16];
__device__ float g_acchp  [BT*4];
__device__ float g_o  [Hc*BT*DVc];
__device__ float g_res[BT*DD];
__device__ float g_frq[16];
__device__ float g_shf[16];

// ---------------- helpers ----------------
__device__ __forceinline__ float sigmoidf_(float x){ return 1.f/(1.f+expf(-x)); }
__device__ __forceinline__ float siluf_(float x){ return x/(1.f+expf(-x)); }
__device__ __forceinline__ float softplusf_(float x){ return fmaxf(x,0.f)+log1pf(expf(-fabsf(x))); }

__device__ __forceinline__ float warpSum(float v){
    #pragma unroll
    for(int o=16;o;o>>=1) v += __shfl_xor_sync(0xffffffffu, v, o);
    return v;
}
__device__ __forceinline__ float blockSum256(float v, float* sred){
    int lane=threadIdx.x&31, wid=threadIdx.x>>5;
    v = warpSum(v);
    if(lane==0) sred[wid]=v;
    __syncthreads();
    if(wid==0){
        float x = (lane<8)? sred[lane] : 0.f;
        x = warpSum(x);
        if(lane==0) sred[0]=x;
    }
    __syncthreads();
    float r = sred[0];
    __syncthreads();
    return r;
}

template<int ACT> __device__ __forceinline__ float actf(float x){
    if(ACT==0) return siluf_(x)*0.125f;
    if(ACT==1) return siluf_(x);
    if(ACT==2) return sigmoidf_(x)*0.125f;
    return x;
}

// ---------------- kernel 0: zero counters ----------------
__global__ void k_zero(){
    int t=threadIdx.x;
    if(t<32){ g_kvcnt[t]=0; g_qcnt[t]=0; }
}

// ---------------- kernel 1: x_hat + route_in + pope constants ----------------
__global__ void k_prep(const float* __restrict__ stream, const float* __restrict__ pope_delta){
    int bt=blockIdx.x, tid=threadIdx.x;
    int b=bt>>10, t=bt&1023;
    __shared__ float sred[8];
    float v[NM]; float ss=0.f;
    #pragma unroll
    for(int n=0;n<NM;n++){
        v[n]=stream[(((b*NM+n)*TT)+t)*DD+tid];
        ss += v[n]*v[n];
    }
    float tot = blockSum256(ss, sred);
    float scale = rsqrtf(tot*(1.f/1024.f) + 1e-6f);
    #pragma unroll
    for(int n=0;n<NM;n++) g_xhat[(size_t)bt*NDc + n*DD + tid] = v[n]*scale;
    g_route[bt*DD+tid] = (v[0]+v[1]+v[2]+v[3])*0.25f;
    if(bt==0 && tid<16){
        g_frq[tid] = (float)pow(10000.0, ((double)tid)/16.0);
        g_shf[tid] = 6.283185307179586f * sigmoidf_(pope_delta[tid]);
    }
}

// ---------------- kernel 1b: fold norm_w into phi tables ----------------
__global__ void k_fold(const float* __restrict__ phi_pre, const float* __restrict__ phi_post,
                       const float* __restrict__ phi_res, const float* __restrict__ mhc_norm_w){
    int g=blockIdx.y;
    int k=blockIdx.x*256+threadIdx.x;
    size_t gk=(size_t)g*NDc+k;
    float nw=mhc_norm_w[gk];
    float* o=g_bfold + gk*32;
    #pragma unroll
    for(int n=0;n<4;n++)  o[n]   = nw*phi_pre [gk*4+n];
    #pragma unroll
    for(int n=0;n<4;n++)  o[4+n] = nw*phi_post[gk*4+n];
    #pragma unroll
    for(int m=0;m<16;m++) o[8+m] = nw*phi_res [gk*16+m];
    #pragma unroll
    for(int n=24;n<32;n++) o[n]=0.f;
}

// ---------------- kernel 2: routing + token lists ----------------
__global__ void k_route(const float* __restrict__ q_router, const float* __restrict__ kv_router){
    int bt=blockIdx.x; int tid=threadIdx.x; int lane=tid&31, h=tid>>5;
    __shared__ float r[DD];
    r[tid]=g_route[bt*DD+tid];
    __syncthreads();
    float aq[4]={0,0,0,0}, ak[4]={0,0,0,0};
    for(int d=lane; d<DD; d+=32){
        float x=r[d];
        const float* wq=q_router + (h*DD+d)*Ec;
        const float* wk=kv_router+ (h*DD+d)*Ec;
        #pragma unroll
        for(int e=0;e<4;e++){ aq[e]+=x*wq[e]; ak[e]+=x*wk[e]; }
    }
    #pragma unroll
    for(int e=0;e<4;e++){ aq[e]=warpSum(aq[e]); ak[e]=warpSum(ak[e]); }
    if(lane==0){
        int bqi=0; float bv=fminf(fmaxf(aq[0],-10.f),10.f);
        #pragma unroll
        for(int e=1;e<4;e++){ float c=fminf(fmaxf(aq[e],-10.f),10.f); if(c>bv){bv=c;bqi=e;} }
        int bki=0; float kvb=fminf(fmaxf(ak[0],-10.f),10.f);
        #pragma unroll
        for(int e=1;e<4;e++){ float c=fminf(fmaxf(ak[e],-10.f),10.f); if(c>kvb){kvb=c;bki=e;} }
        g_qsel [h*BT+bt]=bqi;
        g_kvsel[h*BT+bt]=bki;
        int p=atomicAdd(&g_kvcnt[h*4+bki],1);
        g_kvlist[(h*4+bki)*BT+p]=bt;
        if(bqi!=0){
            int p2=atomicAdd(&g_qcnt[h*4+bqi],1);
            g_qlist[(h*4+bqi)*BT+p2]=bt;
        }
    }
}

// ---------------- grouped GEMM (gathered A rows); AH: A has per-h stride ----------------
template<int KDIM,int NDIM,int ACT,int AH>
__global__ void __launch_bounds__(256) k_ggemm(
    const float* __restrict__ Ab, const float* __restrict__ Bb, float* __restrict__ Ob,
    const int* __restrict__ cnts, const int* __restrict__ lists)
{
    int g = blockIdx.z;
    int cnt = cnts[g];
    int m0 = blockIdx.x*64;
    if(m0>=cnt) return;
    int h = g>>2;
    int n0 = blockIdx.y*64;
    int tid=threadIdx.x;

    __shared__ int stok[64];
    __shared__ float As[16][68];
    __shared__ float Bs[16][68];

    if(tid<64){ int m=m0+tid; stok[tid]=(m<cnt)? lists[g*BT+m] : -1; }
    __syncthreads();

    int am=tid>>2, akq=tid&3;
    int atok=stok[am];
    const float* arow = Ab + ((size_t)(AH?h:0)*BT + (atok<0?0:atok))*KDIM;
    const float* Bg = Bb + (size_t)g*KDIM*NDIM;
    int bkk=tid>>4, bnq=tid&15;
    int tm0=(tid&15)*4, tn0=(tid>>4)*4;

    float acc[4][4]={};
    for(int k0=0;k0<KDIM;k0+=16){
        int ak=k0+akq*4;
        float4 av=make_float4(0,0,0,0);
        if(atok>=0 && ak<KDIM) av=*(const float4*)(arow+ak);
        As[akq*4+0][am]=av.x; As[akq*4+1][am]=av.y;
        As[akq*4+2][am]=av.z; As[akq*4+3][am]=av.w;
        int bk=k0+bkk, bn=n0+bnq*4;
        float4 bv=make_float4(0,0,0,0);
        if(bk<KDIM && bn<NDIM) bv=*(const float4*)(Bg+(size_t)bk*NDIM+bn);
        *(float4*)&Bs[bkk][bnq*4]=bv;
        __syncthreads();
        #pragma unroll
        for(int kk=0;kk<16;kk++){
            float4 a=*(float4*)&As[kk][tm0];
            float4 bb_=*(float4*)&Bs[kk][tn0];
            acc[0][0]+=a.x*bb_.x; acc[0][1]+=a.x*bb_.y; acc[0][2]+=a.x*bb_.z; acc[0][3]+=a.x*bb_.w;
            acc[1][0]+=a.y*bb_.x; acc[1][1]+=a.y*bb_.y; acc[1][2]+=a.y*bb_.z; acc[1][3]+=a.y*bb_.w;
            acc[2][0]+=a.z*bb_.x; acc[2][1]+=a.z*bb_.y; acc[2][2]+=a.z*bb_.z; acc[2][3]+=a.z*bb_.w;
            acc[3][0]+=a.w*bb_.x; acc[3][1]+=a.w*bb_.y; acc[3][2]+=a.w*bb_.z; acc[3][3]+=a.w*bb_.w;
        }
        __syncthreads();
    }
    int nbase=n0+tn0;
    if(nbase<NDIM){
        #pragma unroll
        for(int i=0;i<4;i++){
            int tok=stok[tm0+i];
            if(tok>=0){
                float4 r;
                r.x=actf<ACT>(acc[i][0]); r.y=actf<ACT>(acc[i][1]);
                r.z=actf<ACT>(acc[i][2]); r.w=actf<ACT>(acc[i][3]);
                *(float4*)(Ob + ((size_t)h*BT+tok)*NDIM + nbase) = r;
            }
        }
    }
}

// ---------------- kernel 3: per-token main (sinkhorn from dots, he, q small path) ----------------
__global__ void __launch_bounds__(256) k_main(
    const float* __restrict__ stream,
    const float* __restrict__ Wq,
    const float* __restrict__ lora_A_q, const float* __restrict__ lora_B_q,
    const float* __restrict__ b_pre, const float* __restrict__ b_post, const float* __restrict__ b_res,
    const float* __restrict__ a_pre, const float* __restrict__ a_post, const float* __restrict__ a_res,
    const float* __restrict__ norm_w)
{
    int bt=blockIdx.x, tid=threadIdx.x;
    int b=bt>>10, t=bt&1023;
    int lane=tid&31, wid=tid>>5;

    __shared__ float st[NM][DD];
    __shared__ float she[DD];
    __shared__ float sdk[24], sdq[4];
    __shared__ float sHq[4], sHkv[4];
    __shared__ float skraw[16], slq[4], skvec[16];
    __shared__ float sacc_res[16];
    __shared__ float sacc_hp[4];
    __shared__ float sred[8];

    #pragma unroll
    for(int n=0;n<NM;n++) st[n][tid]=stream[(((b*NM+n)*TT)+t)*DD+tid];
    if(tid<16) sacc_res[tid]=0.f;
    if(tid<4)  sacc_hp[tid]=0.f;
    __syncthreads();

    for(int h=0;h<Hc;h++){
        int eq  = g_qsel [h*BT+bt];
        int ekv = g_kvsel[h*BT+bt];
        int heq = h*Ec+eq, hekv = h*Ec+ekv;

        if(tid<24) sdk[tid]=g_dotkv[((size_t)h*BT+bt)*32+tid];
        if(eq!=0 && tid>=32 && tid<36) sdq[tid-32]=g_dotq[((size_t)h*BT+bt)*32+(tid-32)];
        __syncthreads();

        if(tid==0){
            float apq=a_pre[heq], apk=a_pre[hekv], apo=a_post[hekv], ars=a_res[hekv];
            #pragma unroll
            for(int n=0;n<4;n++){
                if(eq!=0) sHq[n] = sigmoidf_(apq*sdq[n] + b_pre[heq*4+n]);
                sHkv[n] = sigmoidf_(apk*sdk[n]   + b_pre[hekv*4+n]);
                sacc_hp[n] += 2.f*sigmoidf_(apo*sdk[4+n] + b_post[hekv*4+n]);
            }
            float M[16];
            #pragma unroll
            for(int m=0;m<16;m++) M[m]=expf(ars*sdk[8+m] + b_res[hekv*16+m]);
            #pragma unroll
            for(int it=0;it<6;it++){
                #pragma unroll
                for(int i=0;i<4;i++){ float s=M[i*4]+M[i*4+1]+M[i*4+2]+M[i*4+3];
                    M[i*4]/=s; M[i*4+1]/=s; M[i*4+2]/=s; M[i*4+3]/=s; }
                #pragma unroll
                for(int j=0;j<4;j++){ float s=M[j]+M[4+j]+M[8+j]+M[12+j];
                    M[j]/=s; M[4+j]/=s; M[8+j]/=s; M[12+j]/=s; }
            }
            #pragma unroll
            for(int m=0;m<16;m++) sacc_res[m]+=M[m];
        }
        __syncthreads();

        // he for kv expert
        {
            float v=0.f;
            #pragma unroll
            for(int n=0;n<4;n++) v += sHkv[n]*st[n][tid];
            float tot = blockSum256(v*v, sred);
            float sc = rsqrtf(tot*(1.f/256.f)+1e-6f);
            g_hekv[((size_t)h*BT+bt)*DD+tid] = v*sc*norm_w[hekv*DD+tid];
        }

        // Q path
        if(eq!=0){
            {
                float v=0.f;
                #pragma unroll
                for(int n=0;n<4;n++) v += sHq[n]*st[n][tid];
                float tot = blockSum256(v*v, sred);
                float sc = rsqrtf(tot*(1.f/256.f)+1e-6f);
                float hv = v*sc*norm_w[heq*DD+tid];
                she[tid]=hv;
                g_heq[((size_t)h*BT+bt)*DD+tid]=hv;
            }
            __syncthreads();
            if(tid<16){
                const float* w = Wq + (size_t)h*DD*DKc + tid;
                float s=0.f;
                #pragma unroll 8
                for(int d=0;d<DD;d++) s += she[d]*w[d*DKc];
                skraw[tid]=s;
            }
            if(tid>=32 && tid<36){
                int r=tid-32;
                const float* w = lora_A_q + (size_t)heq*DD*Rc + r;
                float s=0.f;
                #pragma unroll 8
                for(int d=0;d<DD;d++) s += she[d]*w[d*Rc];
                slq[r]=siluf_(s);
            }
            __syncthreads();
            if(tid>=64 && tid<80){
                int k=tid-64;
                const float* w = lora_B_q + (size_t)heq*Rc*DKc + k;
                float s=skraw[k];
                #pragma unroll
                for(int r=0;r<Rc;r++) s += slq[r]*w[r*DKc];
                skvec[k]=s;
            }
            __syncthreads();
            if(wid==0){
                float val=(lane<16)? skvec[lane] : 0.f;
                float ss=val*val;
                #pragma unroll
                for(int o=8;o;o>>=1) ss += __shfl_xor_sync(0xffffffffu, ss, o);
                if(lane<16){
                    float nrm=sqrtf(ss);
                    float x=val/fmaxf(nrm,1e-12f);
                    float mu=softplusf_(x);
                    float ph=(float)t*g_frq[lane];
                    size_t tb32=((size_t)h*BT+bt)*DKPc;
                    g_q[tb32+lane]    = mu*cosf(ph);
                    g_q[tb32+16+lane] = mu*sinf(ph);
                }
            }
        } else {
            if(tid<32) g_q[((size_t)h*BT+bt)*DKPc+tid]=0.f;
            g_posth[((size_t)h*BT+bt)*DD+tid]=0.f;
        }
        __syncthreads();
    } // h loop

    if(tid<16) g_accres[bt*16+tid]=sacc_res[tid];
    if(tid<4)  g_acchp [bt*4+tid]=sacc_hp[tid];
}

// ---------------- GEMM: [Wv|Wk] per head, all tokens ----------------
__global__ void __launch_bounds__(256) k_gemm_vk(
    const float* __restrict__ Wv, const float* __restrict__ Wk)
{
    int h = blockIdx.z;
    int m0 = blockIdx.x*64;
    int n0 = blockIdx.y*64;
    int tid=threadIdx.x;
    __shared__ float As[16][68];
    __shared__ float Bs[16][68];

    int am=tid>>2, akq=tid&3;
    const float* arow = g_hekv + ((size_t)h*BT + m0+am)*DD;
    int bkk=tid>>4, bnq=tid&15;
    int tm0=(tid&15)*4, tn0=(tid>>4)*4;

    float acc[4][4]={};
    for(int k0=0;k0<DD;k0+=16){
        int ak=k0+akq*4;
        float4 av=*(const float4*)(arow+ak);
        As[akq*4+0][am]=av.x; As[akq*4+1][am]=av.y;
        As[akq*4+2][am]=av.z; As[akq*4+3][am]=av.w;
        int bk=k0+bkk, bn=n0+bnq*4;
        float4 bv=make_float4(0,0,0,0);
        if(bn<64)      bv=*(const float4*)(Wv+(size_t)h*DD*64 + (size_t)bk*64 + bn);
        else if(bn<80) bv=*(const float4*)(Wk+(size_t)h*DD*16 + (size_t)bk*16 + (bn-64));
        *(float4*)&Bs[bkk][bnq*4]=bv;
        __syncthreads();
        #pragma unroll
        for(int kk=0;kk<16;kk++){
            float4 a=*(float4*)&As[kk][tm0];
            float4 bb_=*(float4*)&Bs[kk][tn0];
            acc[0][0]+=a.x*bb_.x; acc[0][1]+=a.x*bb_.y; acc[0][2]+=a.x*bb_.z; acc[0][3]+=a.x*bb_.w;
            acc[1][0]+=a.y*bb_.x; acc[1][1]+=a.y*bb_.y; acc[1][2]+=a.y*bb_.z; acc[1][3]+=a.y*bb_.w;
            acc[2][0]+=a.z*bb_.x; acc[2][1]+=a.z*bb_.y; acc[2][2]+=a.z*bb_.z; acc[2][3]+=a.z*bb_.w;
            acc[3][0]+=a.w*bb_.x; acc[3][1]+=a.w*bb_.y; acc[3][2]+=a.w*bb_.z; acc[3][3]+=a.w*bb_.w;
        }
        __syncthreads();
    }
    int nbase=n0+tn0;
    if(nbase<80){
        #pragma unroll
        for(int i=0;i<4;i++){
            float4 r=make_float4(acc[i][0],acc[i][1],acc[i][2],acc[i][3]);
            *(float4*)(g_vk + ((size_t)h*BT + m0+tm0+i)*80 + nbase) = r;
        }
    }
}

// ---------------- GEMM: fused [alpha_up|beta_up|loraAk|loraAv] per (h,e) group ----------------
__global__ void __launch_bounds__(256) k_gemm_mid(
    const float* __restrict__ alpha_up, const float* __restrict__ beta_up,
    const float* __restrict__ lora_A_k, const float* __restrict__ lora_A_v)
{
    int g = blockIdx.z;
    int cnt = g_kvcnt[g];
    int m0 = blockIdx.x*64;
    if(m0>=cnt) return;
    int h = g>>2;
    int tid=threadIdx.x;
    __shared__ int stok[64];
    __shared__ float As[16][68];
    __shared__ float Bs[16][68];

    if(tid<64){ int m=m0+tid; stok[tid]=(m<cnt)? g_kvlist[g*BT+m] : -1; }
    __syncthreads();

    int am=tid>>2, akq=tid&3;
    int atok=stok[am];
    const float* arow = g_hekv + ((size_t)h*BT + (atok<0?0:atok))*DD;
    int tm0=(tid&15)*4, tn0=(tid>>4)*4;
    int bn=tid&63, bkb=tid>>6;

    float acc[4][4]={};
    for(int k0=0;k0<DD;k0+=16){
        int ak=k0+akq*4;
        float4 av=make_float4(0,0,0,0);
        if(atok>=0) av=*(const float4*)(arow+ak);
        As[akq*4+0][am]=av.x; As[akq*4+1][am]=av.y;
        As[akq*4+2][am]=av.z; As[akq*4+3][am]=av.w;
        #pragma unroll
        for(int p=0;p<4;p++){
            int kk=bkb+4*p;
            int k=k0+kk;
            float bval=0.f;
            if(bn<25)       bval=alpha_up [(size_t)g*DD*DAc + (size_t)k*DAc + bn];
            else if(bn<50)  bval=beta_up  [(size_t)g*DD*DAc + (size_t)k*DAc + (bn-25)];
            else if(bn<54)  bval=lora_A_k [(size_t)g*DD*Rc  + (size_t)k*Rc  + (bn-50)];
            else if(bn<58)  bval=lora_A_v [(size_t)g*DD*Rc  + (size_t)k*Rc  + (bn-54)];
            Bs[kk][bn]=bval;
        }
        __syncthreads();
        #pragma unroll
        for(int kk=0;kk<16;kk++){
            float4 a=*(float4*)&As[kk][tm0];
            float4 bb_=*(float4*)&Bs[kk][tn0];
            acc[0][0]+=a.x*bb_.x; acc[0][1]+=a.x*bb_.y; acc[0][2]+=a.x*bb_.z; acc[0][3]+=a.x*bb_.w;
            acc[1][0]+=a.y*bb_.x; acc[1][1]+=a.y*bb_.y; acc[1][2]+=a.y*bb_.z; acc[1][3]+=a.y*bb_.w;
            acc[2][0]+=a.z*bb_.x; acc[2][1]+=a.z*bb_.y; acc[2][2]+=a.z*bb_.z; acc[2][3]+=a.z*bb_.w;
            acc[3][0]+=a.w*bb_.x; acc[3][1]+=a.w*bb_.y; acc[3][2]+=a.w*bb_.z; acc[3][3]+=a.w*bb_.w;
        }
        __syncthreads();
    }
    #pragma unroll
    for(int i=0;i<4;i++){
        int tok=stok[tm0+i];
        if(tok>=0){
            float4 r;
            r.x=siluf_(acc[i][0]); r.y=siluf_(acc[i][1]);
            r.z=siluf_(acc[i][2]); r.w=siluf_(acc[i][3]);
            *(float4*)(g_mid + ((size_t)h*BT+tok)*64 + tn0) = r;
        }
    }
}

// ---------------- kernel: finish kv path ----------------
__global__ void __launch_bounds__(64) k_finish(
    const float* __restrict__ alpha_down, const float* __restrict__ beta_down,
    const float* __restrict__ lora_B_k, const float* __restrict__ lora_B_v)
{
    int bt=blockIdx.x, h=blockIdx.y;
    int tid=threadIdx.x;
    int t=bt&1023;
    int ekv=g_kvsel[h*BT+bt];
    int g=h*4+ekv;
    __shared__ float mid[64];
    __shared__ float skv[16];
    size_t row=(size_t)h*BT+bt;
    mid[tid]=g_mid[row*64+tid];
    __syncthreads();

    {
        float s = g_vk[row*80+tid];
        const float* w = lora_B_v + (size_t)g*Rc*DVc + tid;
        #pragma unroll
        for(int r=0;r<Rc;r++) s += mid[54+r]*w[r*DVc];
        g_v[row*DVc+tid]=siluf_(s);
    }
    if(tid<32){
        const float* w = alpha_down + (size_t)g*DAc*DKPc + tid;
        float s=0.f;
        #pragma unroll
        for(int a=0;a<DAc;a++) s += mid[a]*w[a*DKPc];
        g_a[row*DKPc+tid]=sigmoidf_(s);
    } else if(tid==32){
        const float* w = beta_down + (size_t)g*DAc;
        float s=0.f;
        #pragma unroll
        for(int a=0;a<DAc;a++) s += mid[25+a]*w[a];
        g_be[row]=sigmoidf_(s);
    } else if(tid>=40 && tid<56){
        int k=tid-40;
        float s = g_vk[row*80+64+k];
        const float* w = lora_B_k + (size_t)g*Rc*DKc + k;
        #pragma unroll
        for(int r=0;r<Rc;r++) s += mid[50+r]*w[r*DKc];
        skv[k]=s;
    }
    __syncthreads();
    if(tid<32){
        float val=(tid<16)? skv[tid] : 0.f;
        float ss=val*val;
        #pragma unroll
        for(int o=8;o;o>>=1) ss += __shfl_xor_sync(0xffffffffu, ss, o);
        if(tid<16){
            float nrm=sqrtf(ss);
            float x=val/fmaxf(nrm,1e-12f);
            float mu=softplusf_(x);
            float ph=(float)t*g_frq[tid]-g_shf[tid];
            g_k[row*DKPc+tid]    = mu*cosf(ph);
            g_k[row*DKPc+16+tid] = mu*sinf(ph);
        }
    }
}

// ---------------- kernel: KDA recurrence ----------------
__global__ void __launch_bounds__(128) k_rec(){
    int hb = blockIdx.x;
    int warp = threadIdx.x>>5;
    int lane = threadIdx.x&31;
    int e = blockIdx.y*4 + warp;
    size_t b32=(size_t)hb*TT*DKPc, b64=(size_t)hb*TT*DVc, bb=(size_t)hb*TT;
    float S=0.f;
    float qc=g_q[b32+lane], kc=g_k[b32+lane], ac=g_a[b32+lane];
    float vc=g_v[b64+e], bec=g_be[bb];
    for(int t=0;t<TT;t++){
        float qn=0,kn=0,an=0,vn=0,ben=0;
        if(t+1<TT){
            size_t o32=b32+(size_t)(t+1)*DKPc;
            qn=g_q[o32+lane]; kn=g_k[o32+lane]; an=g_a[o32+lane];
            vn=g_v[b64+(size_t)(t+1)*DVc+e]; ben=g_be[bb+t+1];
        }
        float aS = ac*S;
        float p1 = kc*aS, p2=qc*aS, p3=qc*kc;
        #pragma unroll
        for(int o=16;o;o>>=1){
            p1 += __shfl_xor_sync(0xffffffffu,p1,o);
            p2 += __shfl_xor_sync(0xffffffffu,p2,o);
            p3 += __shfl_xor_sync(0xffffffffu,p3,o);
        }
        float w = bec*(vc-p1);
        S = aS + kc*w;
        float o_ = p2 + p3*w;
        if(lane==0) g_o[b64+(size_t)t*DVc+e]=o_;
        qc=qn;kc=kn;ac=an;vc=vn;bec=ben;
    }
}

// ---------------- kernel: result ----------------
__global__ void __launch_bounds__(256) k_result(const float* __restrict__ W_o){
    int bt0=blockIdx.x*16, tid=threadIdx.x;
    __shared__ float A[16][512];
    for(int idx=tid; idx<16*512; idx+=256){
        int r=idx>>9, c=idx&511;
        int bt=bt0+r;
        int hh=c>>6;
        float accp=0.f;
        #pragma unroll
        for(int h2=0;h2<8;h2++) accp += g_preh[((size_t)h2*BT+bt)*DATTNc + c];
        float ov = (g_qsel[hh*BT+bt]==0)? 0.f : g_o[((size_t)hh*BT+bt)*DVc + (c&63)];
        A[r][c] = ov*(1.f/22.627416997969522f)*accp;
    }
    __syncthreads();
    float out[16];
    #pragma unroll
    for(int r=0;r<16;r++) out[r]=0.f;
    for(int c=0;c<512;c+=4){
        float w0=W_o[(size_t)c*DD+tid];
        float w1=W_o[(size_t)(c+1)*DD+tid];
        float w2=W_o[(size_t)(c+2)*DD+tid];
        float w3=W_o[(size_t)(c+3)*DD+tid];
        #pragma unroll
        for(int r=0;r<16;r++){
            float4 a=*(float4*)&A[r][c];
            out[r]+=a.x*w0+a.y*w1+a.z*w2+a.w*w3;
        }
    }
    #pragma unroll
    for(int r=0;r<16;r++){
        int bt=bt0+r;
        float ap=0.f;
        #pragma unroll
        for(int h2=0;h2<8;h2++) ap += g_posth[((size_t)h2*BT+bt)*DD+tid];
        g_res[(size_t)bt*DD+tid]=out[r]*ap;
    }
}

// ---------------- kernel: final stream mixing ----------------
__global__ void k_final(const float* __restrict__ stream, float* __restrict__ out){
    int bt=blockIdx.x, tid=threadIdx.x;
    int b=bt>>10, t=bt&1023;
    __shared__ float sres[16], shp[4];
    if(tid<16) sres[tid]=g_accres[bt*16+tid]*0.125f;
    if(tid<4)  shp[tid] =g_acchp [bt*4+tid]*0.125f;
    __syncthreads();
    float r=g_res[(size_t)bt*DD+tid];
    float st[4];
    #pragma unroll
    for(int j=0;j<4;j++) st[j]=stream[(((b*NM+j)*TT)+t)*DD+tid];
    #pragma unroll
    for(int n=0;n<4;n++){
        float acc = sres[n*4+0]*st[0]+sres[n*4+1]*st[1]+sres[n*4+2]*st[2]+sres[n*4+3]*st[3];
        acc += shp[n]*r;
        out[(((b*NM+n)*TT)+t)*DD+tid]=acc;
    }
}

// ---------------- launch ----------------
extern "C" void kernel_launch(void* const* d_in, const int* in_sizes, int n_in,
                              void* d_out, int out_size){
    const float* stream     =(const float*)d_in[0];
    const float* Wq         =(const float*)d_in[1];
    const float* Wk         =(const float*)d_in[2];
    const float* Wv         =(const float*)d_in[3];
    const float* pope_delta =(const float*)d_in[4];
    const float* q_router   =(const float*)d_in[5];
    const float* kv_router  =(const float*)d_in[6];
    const float* lora_A_q   =(const float*)d_in[7];
    const float* lora_B_q   =(const float*)d_in[8];
    const float* lora_A_k   =(const float*)d_in[9];
    const float* lora_B_k   =(const float*)d_in[10];
    const float* lora_A_v   =(const float*)d_in[11];
    const float* lora_B_v   =(const float*)d_in[12];
    const float* alpha_up   =(const float*)d_in[13];
    const float* alpha_down =(const float*)d_in[14];
    const float* beta_up    =(const float*)d_in[15];
    const float* beta_down  =(const float*)d_in[16];
    const float* mhc_norm_w =(const float*)d_in[17];
    const float* phi_pre    =(const float*)d_in[18];
    const float* phi_post   =(const float*)d_in[19];
    const float* phi_res    =(const float*)d_in[20];
    const float* b_pre      =(const float*)d_in[21];
    const float* b_post     =(const float*)d_in[22];
    const float* b_res      =(const float*)d_in[23];
    const float* a_pre      =(const float*)d_in[24];
    const float* a_post     =(const float*)d_in[25];
    const float* a_res      =(const float*)d_in[26];
    const float* norm_w     =(const float*)d_in[27];
    const float* W_pre      =(const float*)d_in[28];
    const float* W_o        =(const float*)d_in[29];
    const float* W_pg1      =(const float*)d_in[30];
    const float* W_pg2      =(const float*)d_in[31];

    int* kvcnt_p; cudaGetSymbolAddress((void**)&kvcnt_p, g_kvcnt);
    int* qcnt_p;  cudaGetSymbolAddress((void**)&qcnt_p,  g_qcnt);
    int* kvlist_p;cudaGetSymbolAddress((void**)&kvlist_p,g_kvlist);
    int* qlist_p; cudaGetSymbolAddress((void**)&qlist_p, g_qlist);
    float* hekv_p; cudaGetSymbolAddress((void**)&hekv_p, g_hekv);
    float* heq_p;  cudaGetSymbolAddress((void**)&heq_p,  g_heq);
    float* preh_p; cudaGetSymbolAddress((void**)&preh_p, g_preh);
    float* posth_p;cudaGetSymbolAddress((void**)&posth_p,g_posth);
    float* pgmid_p;cudaGetSymbolAddress((void**)&pgmid_p,g_pgmid);
    float* xhat_p; cudaGetSymbolAddress((void**)&xhat_p, g_xhat);
    float* bfold_p;cudaGetSymbolAddress((void**)&bfold_p,g_bfold);
    float* dotkv_p;cudaGetSymbolAddress((void**)&dotkv_p,g_dotkv);
    float* dotq_p; cudaGetSymbolAddress((void**)&dotq_p, g_dotq);

    k_zero <<<1,64>>>();
    k_prep <<<BT,256>>>(stream, pope_delta);
    k_fold <<<dim3(4,32),256>>>(phi_pre, phi_post, phi_res, mhc_norm_w);
    k_route<<<BT,256>>>(q_router, kv_router);
    // dots via grouped GEMM (coalesced, phi fully reused)
    k_ggemm<1024,32,3,0><<<dim3(64,1,32),256>>>(xhat_p, bfold_p, dotkv_p, kvcnt_p, kvlist_p);
    k_ggemm<1024,32,3,0><<<dim3(64,1,32),256>>>(xhat_p, bfold_p, dotq_p,  qcnt_p,  qlist_p);
    k_main <<<BT,256>>>(stream, Wq, lora_A_q, lora_B_q,
                        b_pre, b_post, b_res, a_pre, a_post, a_res, norm_w);
    k_gemm_vk <<<dim3(64,2,8),256>>>(Wv, Wk);
    k_ggemm<256,512,0,1><<<dim3(64,8,32),256>>>(hekv_p, W_pre, preh_p, kvcnt_p, kvlist_p);
    k_gemm_mid<<<dim3(64,1,32),256>>>(alpha_up, beta_up, lora_A_k, lora_A_v);
    k_ggemm<256,316,1,1><<<dim3(64,5,32),256>>>(heq_p, W_pg1, pgmid_p, qcnt_p, qlist_p);
    k_ggemm<316,256,2,1><<<dim3(64,4,32),256>>>(pgmid_p, W_pg2, posth_p, qcnt_p, qlist_p);
    k_finish<<<dim3(BT,Hc),64>>>(alpha_down, beta_down, lora_B_k, lora_B_v);
    k_rec  <<<dim3(32,16),128>>>();
    k_result<<<256,256>>>(W_o);
    k_final <<<BT,256>>>(stream, (float*)d_out);
}